// round 10
// baseline (speedup 1.0000x reference)
#include <cuda_runtime.h>
#include <cuda_bf16.h>

#define DIM        128
#define MAX_ENT    50048
#define MAX_REL    24
#define MAX_NEEDED 4096
#define GROUPS     8
#define EPT        8             // edges per thread in the scan

// ---------------- device scratch (static zero-init == "clean" state) ------
// g_slot[node]: 0 = free, 1 = being claimed, s+2 = assigned slot s
__device__ int          g_is64;
__device__ int          g_slot[MAX_ENT];
__device__ unsigned int g_bits[MAX_ENT / 32];        // membership bitmap
__device__ int          g_needed_nodes[MAX_NEEDED];
__device__ int          g_n_needed;
__device__ unsigned int g_mark_done;                 // producer counter
__device__ float        g_msg[(size_t)MAX_NEEDED * MAX_REL * DIM];
__device__ float        g_cnt[MAX_NEEDED * MAX_REL];
__device__ float        g_agg[MAX_NEEDED * DIM];
__device__ unsigned int g_cntB, g_senseB;            // sense-reversal barrier

__device__ __forceinline__ int ld_idx(const void* p, size_t i, int is64) {
    if (is64) return (int)((const long long*)p)[i];
    return ((const int*)p)[i];
}

// fast tanh: 1 - 2/(e^{2x}+1); rel err ~1e-7
__device__ __forceinline__ float ftanh(float x) {
    float e = __expf(2.0f * x);
    return 1.0f - 2.0f / (e + 1.0f);
}

// Sense-reversal grid barrier; self-resetting (graph-replay safe).
__device__ __forceinline__ void barrier_sr(unsigned int* cnt,
                                           unsigned int* sense,
                                           unsigned int nblk) {
    __threadfence();
    __syncthreads();
    if (threadIdx.x == 0) {
        unsigned int my_sense = *(volatile unsigned int*)sense;
        unsigned int v = atomicAdd(cnt, 1u);
        if (v == nblk - 1u) {
            atomicExch(cnt, 0u);
            __threadfence();
            atomicExch(sense, my_sense ^ 1u);
        } else {
            while (*(volatile unsigned int*)sense == my_sense) { }
        }
        __threadfence();
    }
    __syncthreads();
}

// ============ 1) k_scanm: mark (first blocks) + overlap-wait + edge scan ===
// The mark producers are low-bid blocks (wave 1, never wait on anyone), so
// the g_mark_done spin by other blocks is deadlock-free. Each block issues
// its dst loads BEFORE spinning, so the wait hides under DRAM latency.
__global__ void __launch_bounds__(256)
k_scanm(const void* __restrict__ edge_index,
        const void* __restrict__ edge_type,
        const float* __restrict__ x,
        const void* __restrict__ sample,
        int n_edge, int n_rel, int batch) {
    __shared__ int s_any;
    const int tid = threadIdx.x;
    const int bid = blockIdx.x;

    // local dtype detect: non-negative int64 => high 32-bit words all zero
    if (tid == 0) s_any = 0;
    __syncthreads();
    if (((const unsigned int*)edge_index)[tid * 2 + 1] != 0u) atomicOr(&s_any, 1);
    __syncthreads();
    const int is64 = s_any ? 0 : 1;
    if (bid == 0 && tid == 0) g_is64 = is64;

    // ---- mark/compact by the first mark_blocks blocks ---------------------
    const int mark_blocks = min((batch * 2 + 255) / 256, 148);
    if (bid < mark_blocks) {
        for (int i = bid * 256 + tid; i < batch * 2; i += mark_blocks * 256) {
            int b = i >> 1;
            int c = (i & 1) * 2;                    // sample columns 0 and 2
            int node = ld_idx(sample, (size_t)b * 3 + c, is64);
            if (atomicCAS(&g_slot[node], 0, 1) == 0) {
                int s = atomicAdd(&g_n_needed, 1);
                g_needed_nodes[s] = node;
                atomicOr(&g_bits[node >> 5], 1u << (node & 31));
                g_slot[node] = s + 2;
            }
        }
        __threadfence();
        __syncthreads();
        if (tid == 0) atomicAdd(&g_mark_done, 1u);
    }

    // ---- issue dst loads (independent; overlap with the wait below) ------
    const int t  = bid * 256 + tid;
    const int e0 = t * EPT;
    int dst[EPT];
    int n = 0;
    if (e0 < n_edge) {
        n = (e0 + EPT <= n_edge) ? EPT : (n_edge - e0);
        if (n == EPT) {
            if (!is64) {
                const int4* p = (const int4*)((const int*)edge_index + (size_t)n_edge + e0);
                int4 v0 = p[0], v1 = p[1];
                dst[0]=v0.x; dst[1]=v0.y; dst[2]=v0.z; dst[3]=v0.w;
                dst[4]=v1.x; dst[5]=v1.y; dst[6]=v1.z; dst[7]=v1.w;
            } else {
                const longlong2* p = (const longlong2*)((const long long*)edge_index + (size_t)n_edge + e0);
                longlong2 w0 = p[0], w1 = p[1], w2 = p[2], w3 = p[3];
                dst[0]=(int)w0.x; dst[1]=(int)w0.y; dst[2]=(int)w1.x; dst[3]=(int)w1.y;
                dst[4]=(int)w2.x; dst[5]=(int)w2.y; dst[6]=(int)w3.x; dst[7]=(int)w3.y;
            }
        } else {
            for (int k = 0; k < n; k++)
                dst[k] = ld_idx(edge_index, (size_t)n_edge + e0 + k, is64);
        }
    }

    // ---- wait for mark completion (cheap: producers are wave-1 blocks) ----
    if (tid == 0) {
        while (*(volatile unsigned int*)&g_mark_done < (unsigned int)mark_blocks) { }
        __threadfence();
    }
    __syncthreads();

    if (n == 0) return;

    // ---- bitmap probe + sparse accumulate ---------------------------------
    unsigned int hit = 0;
#pragma unroll
    for (int k = 0; k < EPT; k++) {
        if (k < n && ((g_bits[dst[k] >> 5] >> (dst[k] & 31)) & 1u))
            hit |= 1u << k;
    }
    while (hit) {
        int k = __ffs(hit) - 1;
        hit &= hit - 1;
        int s = g_slot[dst[k]] - 2;
        int e   = e0 + k;
        int r   = ld_idx(edge_type, e, is64);
        int src = ld_idx(edge_index, e, is64);
        atomicAdd(&g_cnt[s * n_rel + r], 1.0f);
        const float4* xs = (const float4*)(x + (size_t)src * DIM);
        float* m = &g_msg[((size_t)s * n_rel + r) * DIM];
#pragma unroll
        for (int j = 0; j < DIM / 4; j++) {
            float4 v = xs[j];
            atomicAdd(&m[4 * j + 0], v.x);
            atomicAdd(&m[4 * j + 1], v.y);
            atomicAdd(&m[4 * j + 2], v.z);
            atomicAdd(&m[4 * j + 3], v.w);
        }
    }
}

// ============ 2) k_gemm: per-(rel, half, slot-group), proven config ========
// grid = (n_rel + 1) * 2 * GROUPS blocks of 128 threads.
__global__ void __launch_bounds__(128)
k_gemm(const float* __restrict__ W_rel,
       const float* __restrict__ W_root,
       const float* __restrict__ x,
       int n_rel) {
    __shared__ float Ws[64 * DIM];   // one 64-col half, Ws[d * 64 + c]
    __shared__ float ms[DIM];

    int idx  = blockIdx.x;
    int r    = idx % (n_rel + 1);
    int half = (idx / (n_rel + 1)) & 1;
    int sg   = idx / ((n_rel + 1) * 2);
    const float* W = (r < n_rel) ? (W_rel + (size_t)r * DIM * DIM) : W_root;
    int tid = threadIdx.x;
    int nn = g_n_needed;

    int fbase = half * 64;
    for (int i = tid; i < 64 * DIM / 4; i += 128) {
        int d = i >> 4, c4 = i & 15;
        ((float4*)Ws)[d * 16 + c4] = *(const float4*)&W[d * DIM + fbase + c4 * 4];
    }
    __syncthreads();

    int c  = tid & 63;
    int dh = (tid >> 6) * 64;

    for (int s = sg; s < nn; s += GROUPS) {
        bool skip = false;
        float scale = 1.0f;
        if (r < n_rel) {
            float cnt = g_cnt[s * n_rel + r];    // uniform across block
            if (cnt == 0.0f) skip = true;
            else scale = 1.0f / cnt;
        }
        if (!skip) {
            if (r < n_rel)
                ms[tid] = g_msg[((size_t)s * n_rel + r) * DIM + tid] * scale;
            else
                ms[tid] = x[(size_t)g_needed_nodes[s] * DIM + tid];
        }
        __syncthreads();
        if (!skip) {
            float acc = 0.0f;
#pragma unroll
            for (int k = 0; k < 16; k++) {
                int d = dh + k * 4;
                float4 mv = *(const float4*)&ms[d];
                acc += mv.x * Ws[(d + 0) * 64 + c];
                acc += mv.y * Ws[(d + 1) * 64 + c];
                acc += mv.z * Ws[(d + 2) * 64 + c];
                acc += mv.w * Ws[(d + 3) * 64 + c];
            }
            atomicAdd(&g_agg[s * DIM + fbase + c], acc);
        }
        __syncthreads();
    }
}

// ============ 3) k_oc: out + msg/cnt zero | barrier | cleanup ==============
// grid = 256 blocks x 256 (co-resident at 2 blocks/SM).
__global__ void __launch_bounds__(256, 2)
k_oc(const void* __restrict__ sample,
     const float* __restrict__ init_rel,
     float* __restrict__ out,
     int batch, int n_rel) {
    const int tid  = threadIdx.x;
    const int gtid = blockIdx.x * 256 + tid;
    const int gsz  = gridDim.x * 256;
    const int nn   = g_n_needed;     // reset happens post-barrier
    const int is64 = g_is64;

    // ---- phase 1a: zero msg/cnt (already consumed by gemm) ----------------
    {
        float4 z = make_float4(0.f, 0.f, 0.f, 0.f);
        int n_msg4 = nn * n_rel * (DIM / 4);
        for (int i = gtid; i < n_msg4; i += gsz) ((float4*)g_msg)[i] = z;
        int n_cnt = nn * n_rel;
        for (int i = gtid; i < n_cnt; i += gsz) g_cnt[i] = 0.0f;
    }

    // ---- phase 1b: warp-per-row gather epilogue ---------------------------
    {
        int w    = gtid >> 5;
        int lane = tid & 31;
        if (w < batch) {
            int sh = 0, st = 0, rel = 0;
            if (lane == 0) {
                int h = ld_idx(sample, (size_t)w * 3 + 0, is64);
                rel   = ld_idx(sample, (size_t)w * 3 + 1, is64);
                int t = ld_idx(sample, (size_t)w * 3 + 2, is64);
                sh = g_slot[h] - 2;
                st = g_slot[t] - 2;
            }
            sh  = __shfl_sync(0xffffffffu, sh, 0);
            st  = __shfl_sync(0xffffffffu, st, 0);
            rel = __shfl_sync(0xffffffffu, rel, 0);

            float4 ah = ((const float4*)g_agg)[sh * (DIM / 4) + lane];
            float4 at = ((const float4*)g_agg)[st * (DIM / 4) + lane];
            float4 rv = ((const float4*)init_rel)[rel * (DIM / 4) + lane];
            float4 o;
            o.x = ftanh(ah.x) * (rv.x * ftanh(at.x));
            o.y = ftanh(ah.y) * (rv.y * ftanh(at.y));
            o.z = ftanh(ah.z) * (rv.z * ftanh(at.z));
            o.w = ftanh(ah.w) * (rv.w * ftanh(at.w));
            ((float4*)out)[(size_t)w * (DIM / 4) + lane] = o;
        }
    }
    barrier_sr(&g_cntB, &g_senseB, gridDim.x);

    // ---- phase 2: cleanup (agg, slot, bits, counters) ----------------------
    {
        float4 z = make_float4(0.f, 0.f, 0.f, 0.f);
        int n_agg4 = nn * (DIM / 4);
        for (int i = gtid; i < n_agg4; i += gsz) ((float4*)g_agg)[i] = z;
        for (int i = gtid; i < nn; i += gsz) {
            int node = g_needed_nodes[i];
            g_slot[node] = 0;
            g_bits[node >> 5] = 0u;   // every set bit belongs to a needed node
        }
        if (gtid == 0) {
            g_n_needed = 0;
            g_mark_done = 0u;         // rearm producer counter for next replay
        }
    }
}

// ---------------- launch ----------------
extern "C" void kernel_launch(void* const* d_in, const int* in_sizes, int n_in,
                              void* d_out, int out_size) {
    const float* init_embed = (const float*)d_in[0];
    const float* init_rel   = (const float*)d_in[1];
    const float* W_rel      = (const float*)d_in[2];
    const float* W_root     = (const float*)d_in[3];
    const void*  edge_index = d_in[4];
    const void*  edge_type  = d_in[5];
    const void*  sample     = d_in[6];
    float* out = (float*)d_out;

    int n_rel  = in_sizes[1] / DIM;
    int n_edge = in_sizes[5];
    int batch  = in_sizes[6] / 3;

    k_scanm<<<(n_edge + EPT * 256 - 1) / (EPT * 256), 256>>>(
        edge_index, edge_type, init_embed, sample, n_edge, n_rel, batch);
    k_gemm <<<(n_rel + 1) * 2 * GROUPS, 128>>>(W_rel, W_root, init_embed, n_rel);
    k_oc   <<<256, 256>>>(sample, init_rel, out, batch, n_rel);
}

// round 11
// speedup vs baseline: 1.1758x; 1.1758x over previous
#include <cuda_runtime.h>
#include <cuda_bf16.h>

#define DIM        128
#define MAX_ENT    50048
#define MAX_REL    24
#define MAX_NEEDED 4096
#define GROUPS     8
#define EPT        8             // edges per thread in the scan

// ---------------- device scratch (static zero-init == "clean" state) ------
// g_slot[node]: 0 = free, 1 = being claimed, s+2 = assigned slot s
__device__ int          g_is64;
__device__ int          g_slot[MAX_ENT];
__device__ unsigned int g_bits[MAX_ENT / 32];        // membership bitmap
__device__ int          g_needed_nodes[MAX_NEEDED];
__device__ int          g_n_needed;
__device__ float        g_msg[(size_t)MAX_NEEDED * MAX_REL * DIM];
__device__ float        g_cnt[MAX_NEEDED * MAX_REL];
__device__ float        g_agg[MAX_NEEDED * DIM];
__device__ unsigned int g_cntB, g_senseB;            // sense-reversal barrier

__device__ __forceinline__ int ld_idx(const void* p, size_t i, int is64) {
    if (is64) return (int)((const long long*)p)[i];
    return ((const int*)p)[i];
}

// fast tanh: 1 - 2/(e^{2x}+1); rel err ~1e-7
__device__ __forceinline__ float ftanh(float x) {
    float e = __expf(2.0f * x);
    return 1.0f - 2.0f / (e + 1.0f);
}

// PDL primitives (sm_90+): wait for predecessor's completion trigger;
// allow dependents to launch early.
__device__ __forceinline__ void pdl_wait() {
    asm volatile("griddepcontrol.wait;" ::: "memory");
}
__device__ __forceinline__ void pdl_trigger() {
    asm volatile("griddepcontrol.launch_dependents;");
}

// Sense-reversal grid barrier; self-resetting (graph-replay safe).
__device__ __forceinline__ void barrier_sr(unsigned int* cnt,
                                           unsigned int* sense,
                                           unsigned int nblk) {
    __threadfence();
    __syncthreads();
    if (threadIdx.x == 0) {
        unsigned int my_sense = *(volatile unsigned int*)sense;
        unsigned int v = atomicAdd(cnt, 1u);
        if (v == nblk - 1u) {
            atomicExch(cnt, 0u);
            __threadfence();
            atomicExch(sense, my_sense ^ 1u);
        } else {
            while (*(volatile unsigned int*)sense == my_sense) { }
        }
        __threadfence();
    }
    __syncthreads();
}

// ============ 1) k_mark: dtype detect + mark + compact =====================
__global__ void k_mark(const unsigned int* __restrict__ ei_words,
                       const void* __restrict__ sample, int batch) {
    __shared__ int s_any;
    if (threadIdx.x == 0) s_any = 0;
    __syncthreads();
    if (ei_words[threadIdx.x * 2 + 1] != 0u) atomicOr(&s_any, 1);
    __syncthreads();
    int is64 = s_any ? 0 : 1;
    if (blockIdx.x == 0 && threadIdx.x == 0) g_is64 = is64;

    int i = blockIdx.x * blockDim.x + threadIdx.x;
    if (i < batch * 2) {
        int b = i >> 1;
        int c = (i & 1) * 2;                        // sample columns 0 and 2
        int node = ld_idx(sample, (size_t)b * 3 + c, is64);
        if (atomicCAS(&g_slot[node], 0, 1) == 0) {  // unique claimer
            int s = atomicAdd(&g_n_needed, 1);
            g_needed_nodes[s] = node;
            atomicOr(&g_bits[node >> 5], 1u << (node & 31));
            g_slot[node] = s + 2;
        }
    }
    pdl_trigger();
}

// ============ 2) k_scan: PDL prologue = dst loads; wait; probe+accumulate ==
__global__ void __launch_bounds__(256)
k_scan(const void* __restrict__ edge_index,
       const void* __restrict__ edge_type,
       const float* __restrict__ x,
       int n_edge, int n_rel) {
    __shared__ int s_any;
    const int tid = threadIdx.x;

    // local dtype detect (input-only; independent of k_mark)
    if (tid == 0) s_any = 0;
    __syncthreads();
    if (((const unsigned int*)edge_index)[tid * 2 + 1] != 0u) atomicOr(&s_any, 1);
    __syncthreads();
    const int is64 = s_any ? 0 : 1;

    // prologue: issue independent dst loads (overlap with k_mark's drain)
    const int t  = blockIdx.x * 256 + tid;
    const int e0 = t * EPT;
    int dst[EPT];
    int n = 0;
    if (e0 < n_edge) {
        n = (e0 + EPT <= n_edge) ? EPT : (n_edge - e0);
        if (n == EPT) {
            if (!is64) {
                const int4* p = (const int4*)((const int*)edge_index + (size_t)n_edge + e0);
                int4 v0 = p[0], v1 = p[1];
                dst[0]=v0.x; dst[1]=v0.y; dst[2]=v0.z; dst[3]=v0.w;
                dst[4]=v1.x; dst[5]=v1.y; dst[6]=v1.z; dst[7]=v1.w;
            } else {
                const longlong2* p = (const longlong2*)((const long long*)edge_index + (size_t)n_edge + e0);
                longlong2 w0 = p[0], w1 = p[1], w2 = p[2], w3 = p[3];
                dst[0]=(int)w0.x; dst[1]=(int)w0.y; dst[2]=(int)w1.x; dst[3]=(int)w1.y;
                dst[4]=(int)w2.x; dst[5]=(int)w2.y; dst[6]=(int)w3.x; dst[7]=(int)w3.y;
            }
        } else {
            for (int k = 0; k < n; k++)
                dst[k] = ld_idx(edge_index, (size_t)n_edge + e0 + k, is64);
        }
    }

    pdl_wait();                  // mark's slot/bits now visible

    if (n > 0) {
        unsigned int hit = 0;
#pragma unroll
        for (int k = 0; k < EPT; k++) {
            if (k < n && ((g_bits[dst[k] >> 5] >> (dst[k] & 31)) & 1u))
                hit |= 1u << k;
        }
        while (hit) {
            int k = __ffs(hit) - 1;
            hit &= hit - 1;
            int s = g_slot[dst[k]] - 2;
            int e   = e0 + k;
            int r   = ld_idx(edge_type, e, is64);
            int src = ld_idx(edge_index, e, is64);
            atomicAdd(&g_cnt[s * n_rel + r], 1.0f);
            const float4* xs = (const float4*)(x + (size_t)src * DIM);
            float* m = &g_msg[((size_t)s * n_rel + r) * DIM];
#pragma unroll
            for (int j = 0; j < DIM / 4; j++) {
                float4 v = xs[j];
                atomicAdd(&m[4 * j + 0], v.x);
                atomicAdd(&m[4 * j + 1], v.y);
                atomicAdd(&m[4 * j + 2], v.z);
                atomicAdd(&m[4 * j + 3], v.w);
            }
        }
    }
    pdl_trigger();
}

// ============ 3) k_gemm: PDL prologue = W staging; wait; compute ===========
// grid = (n_rel + 1) * 2 * GROUPS blocks of 128 threads.
__global__ void __launch_bounds__(128)
k_gemm(const float* __restrict__ W_rel,
       const float* __restrict__ W_root,
       const float* __restrict__ x,
       int n_rel) {
    __shared__ float Ws[64 * DIM];   // one 64-col half, Ws[d * 64 + c]
    __shared__ float ms[DIM];

    int idx  = blockIdx.x;
    int r    = idx % (n_rel + 1);
    int half = (idx / (n_rel + 1)) & 1;
    int sg   = idx / ((n_rel + 1) * 2);
    const float* W = (r < n_rel) ? (W_rel + (size_t)r * DIM * DIM) : W_root;
    int tid = threadIdx.x;

    // prologue: stage W tile (input-only; overlaps scan's drain)
    int fbase = half * 64;
    for (int i = tid; i < 64 * DIM / 4; i += 128) {
        int d = i >> 4, c4 = i & 15;
        ((float4*)Ws)[d * 16 + c4] = *(const float4*)&W[d * DIM + fbase + c4 * 4];
    }
    __syncthreads();

    pdl_wait();                  // scan's msg/cnt now visible
    int nn = g_n_needed;

    int c  = tid & 63;
    int dh = (tid >> 6) * 64;

    for (int s = sg; s < nn; s += GROUPS) {
        bool skip = false;
        float scale = 1.0f;
        if (r < n_rel) {
            float cnt = g_cnt[s * n_rel + r];    // uniform across block
            if (cnt == 0.0f) skip = true;
            else scale = 1.0f / cnt;
        }
        if (!skip) {
            if (r < n_rel)
                ms[tid] = g_msg[((size_t)s * n_rel + r) * DIM + tid] * scale;
            else
                ms[tid] = x[(size_t)g_needed_nodes[s] * DIM + tid];
        }
        __syncthreads();
        if (!skip) {
            float acc = 0.0f;
#pragma unroll
            for (int k = 0; k < 16; k++) {
                int d = dh + k * 4;
                float4 mv = *(const float4*)&ms[d];
                acc += mv.x * Ws[(d + 0) * 64 + c];
                acc += mv.y * Ws[(d + 1) * 64 + c];
                acc += mv.z * Ws[(d + 2) * 64 + c];
                acc += mv.w * Ws[(d + 3) * 64 + c];
            }
            atomicAdd(&g_agg[s * DIM + fbase + c], acc);
        }
        __syncthreads();
    }
    pdl_trigger();
}

// ============ 4) k_oc: PDL prologue = index gathers; wait; out | cleanup ===
// grid = 256 blocks x 256 (co-resident at 2 blocks/SM).
__global__ void __launch_bounds__(256, 2)
k_oc(const void* __restrict__ sample,
     const float* __restrict__ init_rel,
     float* __restrict__ out,
     int batch, int n_rel) {
    const int tid  = threadIdx.x;
    const int gtid = blockIdx.x * 256 + tid;
    const int gsz  = gridDim.x * 256;

    // prologue: sample + slot gathers (slot/bits stable since k_mark,
    // which completed before k_scan ended; g_is64 / g_n_needed likewise)
    const int nn   = g_n_needed;
    const int is64 = g_is64;
    int w    = gtid >> 5;
    int lane = tid & 31;
    int sh = 0, st = 0, rel = 0;
    float4 rv = make_float4(0.f, 0.f, 0.f, 0.f);
    if (w < batch) {
        if (lane == 0) {
            int h = ld_idx(sample, (size_t)w * 3 + 0, is64);
            rel   = ld_idx(sample, (size_t)w * 3 + 1, is64);
            int t = ld_idx(sample, (size_t)w * 3 + 2, is64);
            sh = g_slot[h] - 2;
            st = g_slot[t] - 2;
        }
        sh  = __shfl_sync(0xffffffffu, sh, 0);
        st  = __shfl_sync(0xffffffffu, st, 0);
        rel = __shfl_sync(0xffffffffu, rel, 0);
        rv  = ((const float4*)init_rel)[rel * (DIM / 4) + lane];
    }

    pdl_wait();                  // gemm's agg now visible

    // out + msg/cnt zeroing (msg/cnt already consumed by gemm)
    {
        float4 z = make_float4(0.f, 0.f, 0.f, 0.f);
        int n_msg4 = nn * n_rel * (DIM / 4);
        for (int i = gtid; i < n_msg4; i += gsz) ((float4*)g_msg)[i] = z;
        int n_cnt = nn * n_rel;
        for (int i = gtid; i < n_cnt; i += gsz) g_cnt[i] = 0.0f;

        if (w < batch) {
            float4 ah = ((const float4*)g_agg)[sh * (DIM / 4) + lane];
            float4 at = ((const float4*)g_agg)[st * (DIM / 4) + lane];
            float4 o;
            o.x = ftanh(ah.x) * (rv.x * ftanh(at.x));
            o.y = ftanh(ah.y) * (rv.y * ftanh(at.y));
            o.z = ftanh(ah.z) * (rv.z * ftanh(at.z));
            o.w = ftanh(ah.w) * (rv.w * ftanh(at.w));
            ((float4*)out)[(size_t)w * (DIM / 4) + lane] = o;
        }
    }
    barrier_sr(&g_cntB, &g_senseB, gridDim.x);

    // cleanup (agg, slot, bits, counter) — restores all-zero invariant
    {
        float4 z = make_float4(0.f, 0.f, 0.f, 0.f);
        int n_agg4 = nn * (DIM / 4);
        for (int i = gtid; i < n_agg4; i += gsz) ((float4*)g_agg)[i] = z;
        for (int i = gtid; i < nn; i += gsz) {
            int node = g_needed_nodes[i];
            g_slot[node] = 0;
            g_bits[node >> 5] = 0u;   // every set bit belongs to a needed node
        }
        if (gtid == 0) g_n_needed = 0;
    }
}

// ---------------- launch (PDL-chained) ----------------
template <typename... Args>
static inline void launch_pdl(void (*kern)(Args...), dim3 grid, dim3 block,
                              bool pdl_secondary, Args... args) {
    cudaLaunchConfig_t cfg = {};
    cfg.gridDim = grid;
    cfg.blockDim = block;
    cfg.dynamicSmemBytes = 0;
    cfg.stream = 0;
    cudaLaunchAttribute attr[1];
    if (pdl_secondary) {
        attr[0].id = cudaLaunchAttributeProgrammaticStreamSerialization;
        attr[0].val.programmaticStreamSerializationAllowed = 1;
        cfg.attrs = attr;
        cfg.numAttrs = 1;
    }
    cudaLaunchKernelEx(&cfg, kern, args...);
}

extern "C" void kernel_launch(void* const* d_in, const int* in_sizes, int n_in,
                              void* d_out, int out_size) {
    const float* init_embed = (const float*)d_in[0];
    const float* init_rel   = (const float*)d_in[1];
    const float* W_rel      = (const float*)d_in[2];
    const float* W_root     = (const float*)d_in[3];
    const void*  edge_index = d_in[4];
    const void*  edge_type  = d_in[5];
    const void*  sample     = d_in[6];
    float* out = (float*)d_out;

    int n_rel  = in_sizes[1] / DIM;
    int n_edge = in_sizes[5];
    int batch  = in_sizes[6] / 3;

    launch_pdl(k_mark, dim3((batch * 2 + 255) / 256), dim3(256), false,
               (const unsigned int*)edge_index, sample, batch);
    launch_pdl(k_scan, dim3((n_edge + EPT * 256 - 1) / (EPT * 256)), dim3(256), true,
               edge_index, edge_type, (const float*)init_embed, n_edge, n_rel);
    launch_pdl(k_gemm, dim3((n_rel + 1) * 2 * GROUPS), dim3(128), true,
               W_rel, W_root, (const float*)init_embed, n_rel);
    launch_pdl(k_oc, dim3(256), dim3(256), true,
               sample, (const float*)init_rel, out, batch, n_rel);
}

// round 12
// speedup vs baseline: 1.3049x; 1.1098x over previous
#include <cuda_runtime.h>
#include <cuda_bf16.h>

#define DIM        128
#define MAX_ENT    50048
#define MAX_REL    24
#define MAX_NEEDED 4096
#define MAX_BATCH  4096
#define GROUPS     8
#define EPT        8             // edges per thread in the scan

// ---------------- device scratch (static zero-init == "clean" state) ------
// g_slot[node]: 0 = free, 1 = being claimed, s+2 = assigned slot s
__device__ unsigned int g_epoch;                     // bumped once per call (k_mark)
__device__ int          g_is64;
__device__ int          g_slot[MAX_ENT];
__device__ unsigned int g_bits[MAX_ENT / 32];        // membership bitmap
__device__ int          g_needed_nodes[MAX_NEEDED];
__device__ int          g_n_needed;
__device__ int          g_hs[MAX_BATCH];             // translated sample slots
__device__ int          g_ts[MAX_BATCH];
__device__ int          g_rel[MAX_BATCH];
__device__ float        g_msg[(size_t)MAX_NEEDED * MAX_REL * DIM];
__device__ float        g_cnt[MAX_NEEDED * MAX_REL];
__device__ float        g_agg[2][MAX_NEEDED * DIM];  // parity double-buffer

__device__ __forceinline__ int ld_idx(const void* p, size_t i, int is64) {
    if (is64) return (int)((const long long*)p)[i];
    return ((const int*)p)[i];
}

// fast tanh: 1 - 2/(e^{2x}+1); rel err ~1e-7
__device__ __forceinline__ float ftanh(float x) {
    float e = __expf(2.0f * x);
    return 1.0f - 2.0f / (e + 1.0f);
}

// PDL primitives (sm_90+)
__device__ __forceinline__ void pdl_wait() {
    asm volatile("griddepcontrol.wait;" ::: "memory");
}
__device__ __forceinline__ void pdl_trigger() {
    asm volatile("griddepcontrol.launch_dependents;");
}

// ============ 1) k_mark: epoch bump + dtype detect + mark + compact ========
__global__ void k_mark(const unsigned int* __restrict__ ei_words,
                       const void* __restrict__ sample, int batch) {
    __shared__ int s_any;
    if (threadIdx.x == 0) s_any = 0;
    __syncthreads();
    if (ei_words[threadIdx.x * 2 + 1] != 0u) atomicOr(&s_any, 1);
    __syncthreads();
    int is64 = s_any ? 0 : 1;
    if (blockIdx.x == 0 && threadIdx.x == 0) {
        g_is64 = is64;
        atomicAdd(&g_epoch, 1u);        // nothing else reads epoch this kernel
    }

    int i = blockIdx.x * blockDim.x + threadIdx.x;
    if (i < batch * 2) {
        int b = i >> 1;
        int c = (i & 1) * 2;                        // sample columns 0 and 2
        int node = ld_idx(sample, (size_t)b * 3 + c, is64);
        if (atomicCAS(&g_slot[node], 0, 1) == 0) {  // unique claimer
            int s = atomicAdd(&g_n_needed, 1);
            g_needed_nodes[s] = node;
            atomicOr(&g_bits[node >> 5], 1u << (node & 31));
            g_slot[node] = s + 2;
        }
    }
    pdl_trigger();
}

// ============ 2) k_scan: prologue dst loads | wait | translate + scan ======
__global__ void __launch_bounds__(256)
k_scan(const void* __restrict__ edge_index,
       const void* __restrict__ edge_type,
       const float* __restrict__ x,
       const void* __restrict__ sample,
       int n_edge, int n_rel, int batch) {
    __shared__ int s_any;
    const int tid = threadIdx.x;
    const int bid = blockIdx.x;

    // local dtype detect (input-only; independent of k_mark)
    if (tid == 0) s_any = 0;
    __syncthreads();
    if (((const unsigned int*)edge_index)[tid * 2 + 1] != 0u) atomicOr(&s_any, 1);
    __syncthreads();
    const int is64 = s_any ? 0 : 1;

    // prologue: issue independent dst loads (overlap with k_mark's drain)
    const int t  = bid * 256 + tid;
    const int e0 = t * EPT;
    int dst[EPT];
    int n = 0;
    if (e0 < n_edge) {
        n = (e0 + EPT <= n_edge) ? EPT : (n_edge - e0);
        if (n == EPT) {
            if (!is64) {
                const int4* p = (const int4*)((const int*)edge_index + (size_t)n_edge + e0);
                int4 v0 = p[0], v1 = p[1];
                dst[0]=v0.x; dst[1]=v0.y; dst[2]=v0.z; dst[3]=v0.w;
                dst[4]=v1.x; dst[5]=v1.y; dst[6]=v1.z; dst[7]=v1.w;
            } else {
                const longlong2* p = (const longlong2*)((const long long*)edge_index + (size_t)n_edge + e0);
                longlong2 w0 = p[0], w1 = p[1], w2 = p[2], w3 = p[3];
                dst[0]=(int)w0.x; dst[1]=(int)w0.y; dst[2]=(int)w1.x; dst[3]=(int)w1.y;
                dst[4]=(int)w2.x; dst[5]=(int)w2.y; dst[6]=(int)w3.x; dst[7]=(int)w3.y;
            }
        } else {
            for (int k = 0; k < n; k++)
                dst[k] = ld_idx(edge_index, (size_t)n_edge + e0 + k, is64);
        }
    }

    pdl_wait();                  // mark's slot/bits now visible

    // sample -> slot translation (first blocks; slots are final now)
    if (t < batch) {
        int h = ld_idx(sample, (size_t)t * 3 + 0, is64);
        int r = ld_idx(sample, (size_t)t * 3 + 1, is64);
        int q = ld_idx(sample, (size_t)t * 3 + 2, is64);
        g_hs[t]  = g_slot[h] - 2;
        g_rel[t] = r;
        g_ts[t]  = g_slot[q] - 2;
    }

    if (n > 0) {
        unsigned int hit = 0;
#pragma unroll
        for (int k = 0; k < EPT; k++) {
            if (k < n && ((g_bits[dst[k] >> 5] >> (dst[k] & 31)) & 1u))
                hit |= 1u << k;
        }
        while (hit) {
            int k = __ffs(hit) - 1;
            hit &= hit - 1;
            int s = g_slot[dst[k]] - 2;
            int e   = e0 + k;
            int r   = ld_idx(edge_type, e, is64);
            int src = ld_idx(edge_index, e, is64);
            atomicAdd(&g_cnt[s * n_rel + r], 1.0f);
            const float4* xs = (const float4*)(x + (size_t)src * DIM);
            float* m = &g_msg[((size_t)s * n_rel + r) * DIM];
#pragma unroll
            for (int j = 0; j < DIM / 4; j++) {
                float4 v = xs[j];
                atomicAdd(&m[4 * j + 0], v.x);
                atomicAdd(&m[4 * j + 1], v.y);
                atomicAdd(&m[4 * j + 2], v.z);
                atomicAdd(&m[4 * j + 3], v.w);
            }
        }
    }
    pdl_trigger();
}

// ============ 3) k_gemm: prologue W staging | wait | compute ===============
// grid = (n_rel + 1) * 2 * GROUPS blocks of 128 threads.
__global__ void __launch_bounds__(128)
k_gemm(const float* __restrict__ W_rel,
       const float* __restrict__ W_root,
       const float* __restrict__ x,
       int n_rel) {
    __shared__ float Ws[64 * DIM];   // one 64-col half, Ws[d * 64 + c]
    __shared__ float ms[DIM];

    int idx  = blockIdx.x;
    int r    = idx % (n_rel + 1);
    int half = (idx / (n_rel + 1)) & 1;
    int sg   = idx / ((n_rel + 1) * 2);
    const float* W = (r < n_rel) ? (W_rel + (size_t)r * DIM * DIM) : W_root;
    int tid = threadIdx.x;

    // prologue: stage W tile (input-only; overlaps scan's drain)
    int fbase = half * 64;
    for (int i = tid; i < 64 * DIM / 4; i += 128) {
        int d = i >> 4, c4 = i & 15;
        ((float4*)Ws)[d * 16 + c4] = *(const float4*)&W[d * DIM + fbase + c4 * 4];
    }
    __syncthreads();

    pdl_wait();                  // scan's msg/cnt now visible
    int nn = g_n_needed;
    float* agg = g_agg[g_epoch & 1u];   // epoch stable since k_mark

    int c  = tid & 63;
    int dh = (tid >> 6) * 64;

    for (int s = sg; s < nn; s += GROUPS) {
        bool skip = false;
        float scale = 1.0f;
        if (r < n_rel) {
            float cnt = g_cnt[s * n_rel + r];    // uniform across block
            if (cnt == 0.0f) skip = true;
            else scale = 1.0f / cnt;
        }
        if (!skip) {
            if (r < n_rel)
                ms[tid] = g_msg[((size_t)s * n_rel + r) * DIM + tid] * scale;
            else
                ms[tid] = x[(size_t)g_needed_nodes[s] * DIM + tid];
        }
        __syncthreads();
        if (!skip) {
            float acc = 0.0f;
#pragma unroll
            for (int k = 0; k < 16; k++) {
                int d = dh + k * 4;
                float4 mv = *(const float4*)&ms[d];
                acc += mv.x * Ws[(d + 0) * 64 + c];
                acc += mv.y * Ws[(d + 1) * 64 + c];
                acc += mv.z * Ws[(d + 2) * 64 + c];
                acc += mv.w * Ws[(d + 3) * 64 + c];
            }
            atomicAdd(&agg[s * DIM + fbase + c], acc);
        }
        __syncthreads();
    }
    pdl_trigger();
}

// ============ 4) k_oc: prologue gathers | wait | out ∥ cleanup (no barrier) =
// grid = 256 blocks x 256 (one co-resident wave at 2 blocks/SM).
__global__ void __launch_bounds__(256, 2)
k_oc(const float* __restrict__ init_rel,
     float* __restrict__ out,
     int batch, int n_rel) {
    const int tid  = threadIdx.x;
    const int gtid = blockIdx.x * 256 + tid;
    const int gsz  = gridDim.x * 256;

    // prologue: translated indices + init_rel row (all stable pre-gemm)
    const int nn = g_n_needed;
    const unsigned int par = g_epoch & 1u;
    int w    = gtid >> 5;
    int lane = tid & 31;
    int sh = 0, st = 0;
    float4 rv = make_float4(0.f, 0.f, 0.f, 0.f);
    if (w < batch) {
        if (lane == 0) { sh = g_hs[w]; st = g_ts[w]; }
        int rel = g_rel[w];                      // uniform-ish; cheap load
        sh  = __shfl_sync(0xffffffffu, sh, 0);
        st  = __shfl_sync(0xffffffffu, st, 0);
        rel = __shfl_sync(0xffffffffu, rel, 0);
        rv  = ((const float4*)init_rel)[rel * (DIM / 4) + lane];
    }

    pdl_wait();                  // gemm's agg now visible

    // ---- out (reads agg[par]) ----------------------------------------------
    if (w < batch) {
        const float4* agg4 = (const float4*)g_agg[par];
        float4 ah = agg4[sh * (DIM / 4) + lane];
        float4 at = agg4[st * (DIM / 4) + lane];
        float4 o;
        o.x = ftanh(ah.x) * (rv.x * ftanh(at.x));
        o.y = ftanh(ah.y) * (rv.y * ftanh(at.y));
        o.z = ftanh(ah.z) * (rv.z * ftanh(at.z));
        o.w = ftanh(ah.w) * (rv.w * ftanh(at.w));
        ((float4*)out)[(size_t)w * (DIM / 4) + lane] = o;
    }

    // ---- cleanup, concurrent with out (disjoint data; no barrier needed) ---
    {
        float4 z = make_float4(0.f, 0.f, 0.f, 0.f);
        float4* msg4 = (float4*)g_msg;
        int n_msg4 = nn * n_rel * (DIM / 4);
        for (int i = gtid; i < n_msg4; i += gsz) msg4[i] = z;
        int n_cnt = nn * n_rel;
        for (int i = gtid; i < n_cnt; i += gsz) g_cnt[i] = 0.0f;
        float4* agg_next = (float4*)g_agg[1u - par];   // next call's buffer
        int n_agg4 = nn * (DIM / 4);
        for (int i = gtid; i < n_agg4; i += gsz) agg_next[i] = z;
        for (int i = gtid; i < nn; i += gsz) {
            int node = g_needed_nodes[i];
            g_slot[node] = 0;
            g_bits[node >> 5] = 0u;   // every set bit belongs to a needed node
        }
        if (gtid == 0) g_n_needed = 0;
    }
}

// ---------------- launch (PDL-chained) ----------------
template <typename... Args>
static inline void launch_pdl(void (*kern)(Args...), dim3 grid, dim3 block,
                              bool pdl_secondary, Args... args) {
    cudaLaunchConfig_t cfg = {};
    cfg.gridDim = grid;
    cfg.blockDim = block;
    cfg.dynamicSmemBytes = 0;
    cfg.stream = 0;
    cudaLaunchAttribute attr[1];
    if (pdl_secondary) {
        attr[0].id = cudaLaunchAttributeProgrammaticStreamSerialization;
        attr[0].val.programmaticStreamSerializationAllowed = 1;
        cfg.attrs = attr;
        cfg.numAttrs = 1;
    }
    cudaLaunchKernelEx(&cfg, kern, args...);
}

extern "C" void kernel_launch(void* const* d_in, const int* in_sizes, int n_in,
                              void* d_out, int out_size) {
    const float* init_embed = (const float*)d_in[0];
    const float* init_rel   = (const float*)d_in[1];
    const float* W_rel      = (const float*)d_in[2];
    const float* W_root     = (const float*)d_in[3];
    const void*  edge_index = d_in[4];
    const void*  edge_type  = d_in[5];
    const void*  sample     = d_in[6];
    float* out = (float*)d_out;

    int n_rel  = in_sizes[1] / DIM;
    int n_edge = in_sizes[5];
    int batch  = in_sizes[6] / 3;

    launch_pdl(k_mark, dim3((batch * 2 + 255) / 256), dim3(256), false,
               (const unsigned int*)edge_index, sample, batch);
    launch_pdl(k_scan, dim3((n_edge + EPT * 256 - 1) / (EPT * 256)), dim3(256), true,
               edge_index, edge_type, (const float*)init_embed, sample,
               n_edge, n_rel, batch);
    launch_pdl(k_gemm, dim3((n_rel + 1) * 2 * GROUPS), dim3(128), true,
               W_rel, W_root, (const float*)init_embed, n_rel);
    launch_pdl(k_oc, dim3(256), dim3(256), true,
               (const float*)init_rel, out, batch, n_rel);
}